// round 5
// baseline (speedup 1.0000x reference)
#include <cuda_runtime.h>
#include <cuda_bf16.h>
#include <stdint.h>
#include <math_constants.h>

#define BATCH 2
#define SEQ   2048
#define EMB   1024
#define NH    16
#define HD    64
#define TOK   4096
#define QKVF  3072
#define NROWS (BATCH * NH * SEQ)          // 65536 softmax rows
#define OUT_ELEMS ((size_t)TOK * EMB)

__device__ float g_qkv[(size_t)TOK * QKVF];   // 50 MB scratch
__device__ float g_ao [(size_t)TOK * EMB];    // 16 MB scratch
__device__ float g_rowsum[NROWS];             // per-row exp sums

// ---------------------------------------------------------------------------
// helpers
// ---------------------------------------------------------------------------
__device__ __forceinline__ void mma_bf16(float* c, const uint32_t* a, uint32_t b0, uint32_t b1) {
    asm volatile(
        "mma.sync.aligned.m16n8k16.row.col.f32.bf16.bf16.f32 "
        "{%0,%1,%2,%3}, {%4,%5,%6,%7}, {%8,%9}, {%0,%1,%2,%3};"
        : "+f"(c[0]), "+f"(c[1]), "+f"(c[2]), "+f"(c[3])
        : "r"(a[0]), "r"(a[1]), "r"(a[2]), "r"(a[3]), "r"(b0), "r"(b1));
}

__device__ __forceinline__ void split2(float x, float y, uint32_t& hi, uint32_t& lo) {
    __nv_bfloat16 bx = __float2bfloat16_rn(x), by = __float2bfloat16_rn(y);
    float rx = x - __bfloat162float(bx);
    float ry = y - __bfloat162float(by);
    __nv_bfloat162 h; h.x = bx; h.y = by;
    __nv_bfloat162 l = __floats2bfloat162_rn(rx, ry);
    hi = *reinterpret_cast<uint32_t*>(&h);
    lo = *reinterpret_cast<uint32_t*>(&l);
}

#define STRB 72   // smem row stride bytes (32 bf16 + pad)

// ---------------------------------------------------------------------------
// zero rowsums (graph-replay safe)
// ---------------------------------------------------------------------------
__global__ void zero_rowsum_kernel() {
    g_rowsum[blockIdx.x * 256 + threadIdx.x] = 0.f;
}

// ---------------------------------------------------------------------------
// C[M,N] = A[M,K] @ W[N,K]^T + bias.  Block 128x128, BK=32, 8 warps (2x4).
// (unchanged from R3 — known good)
// ---------------------------------------------------------------------------
__global__ void __launch_bounds__(256) mma_gemm_bias(
    const float* __restrict__ A, const float* __restrict__ W,
    const float* __restrict__ bias, float* __restrict__ C, int N, int K)
{
    __shared__ __align__(16) char sAh[128 * STRB];
    __shared__ __align__(16) char sAl[128 * STRB];
    __shared__ __align__(16) char sBh[128 * STRB];
    __shared__ __align__(16) char sBl[128 * STRB];

    const int tid = threadIdx.x;
    const int lane = tid & 31, wid = tid >> 5;
    const int warp_m = wid >> 2, warp_n = wid & 3;
    const int bm = blockIdx.y * 128, bn = blockIdx.x * 128;
    const int row = tid >> 1, kq = (tid & 1) * 16;
    const int r4 = lane >> 2, c4 = (lane & 3);

    float acc[4][4][4];
#pragma unroll
    for (int i = 0; i < 4; i++)
#pragma unroll
        for (int j = 0; j < 4; j++)
#pragma unroll
            for (int l = 0; l < 4; l++) acc[i][j][l] = 0.f;

    for (int kt = 0; kt < (K >> 5); kt++) {
        const float* Ap = A + (size_t)(bm + row) * K + kt * 32 + kq;
        const float* Wp = W + (size_t)(bn + row) * K + kt * 32 + kq;
        float4 av[4], wv[4];
#pragma unroll
        for (int i = 0; i < 4; i++) av[i] = *(const float4*)(Ap + i * 4);
#pragma unroll
        for (int i = 0; i < 4; i++) wv[i] = *(const float4*)(Wp + i * 4);
        __syncthreads();
#pragma unroll
        for (int i = 0; i < 4; i++) {
            uint32_t h0, l0, h1, l1;
            split2(av[i].x, av[i].y, h0, l0);
            split2(av[i].z, av[i].w, h1, l1);
            uint32_t off = row * STRB + (kq + i * 4) * 2;
            *(uint2*)(sAh + off) = make_uint2(h0, h1);
            *(uint2*)(sAl + off) = make_uint2(l0, l1);
            split2(wv[i].x, wv[i].y, h0, l0);
            split2(wv[i].z, wv[i].w, h1, l1);
            *(uint2*)(sBh + off) = make_uint2(h0, h1);
            *(uint2*)(sBl + off) = make_uint2(l0, l1);
        }
        __syncthreads();

#pragma unroll
        for (int s = 0; s < 2; s++) {
            const int kb = s * 32;
            uint32_t Ah[4][4], Al[4][4];
#pragma unroll
            for (int fm = 0; fm < 4; fm++) {
                uint32_t base = (warp_m * 64 + fm * 16 + r4) * STRB + kb + c4 * 4;
                Ah[fm][0] = *(const uint32_t*)(sAh + base);
                Ah[fm][1] = *(const uint32_t*)(sAh + base + 8 * STRB);
                Ah[fm][2] = *(const uint32_t*)(sAh + base + 16);
                Ah[fm][3] = *(const uint32_t*)(sAh + base + 8 * STRB + 16);
                Al[fm][0] = *(const uint32_t*)(sAl + base);
                Al[fm][1] = *(const uint32_t*)(sAl + base + 8 * STRB);
                Al[fm][2] = *(const uint32_t*)(sAl + base + 16);
                Al[fm][3] = *(const uint32_t*)(sAl + base + 8 * STRB + 16);
            }
#pragma unroll
            for (int fn = 0; fn < 4; fn++) {
                uint32_t bb = (warp_n * 32 + fn * 8 + r4) * STRB + kb + c4 * 4;
                uint32_t Bh0 = *(const uint32_t*)(sBh + bb);
                uint32_t Bh1 = *(const uint32_t*)(sBh + bb + 16);
                uint32_t Bl0 = *(const uint32_t*)(sBl + bb);
                uint32_t Bl1 = *(const uint32_t*)(sBl + bb + 16);
#pragma unroll
                for (int fm = 0; fm < 4; fm++) {
                    mma_bf16(acc[fm][fn], Ah[fm], Bh0, Bh1);
                    mma_bf16(acc[fm][fn], Ah[fm], Bl0, Bl1);
                    mma_bf16(acc[fm][fn], Al[fm], Bh0, Bh1);
                }
            }
        }
    }

    const int cq = (lane & 3) * 2;
#pragma unroll
    for (int fm = 0; fm < 4; fm++) {
#pragma unroll
        for (int fn = 0; fn < 4; fn++) {
            int row0 = bm + warp_m * 64 + fm * 16 + r4;
            int col  = bn + warp_n * 32 + fn * 8 + cq;
            float b0 = bias[col], b1 = bias[col + 1];
            *(float2*)(C + (size_t)row0 * N + col) =
                make_float2(acc[fm][fn][0] + b0, acc[fm][fn][1] + b1);
            *(float2*)(C + (size_t)(row0 + 8) * N + col) =
                make_float2(acc[fm][fn][2] + b0, acc[fm][fn][3] + b1);
        }
    }
}

// ---------------------------------------------------------------------------
// Scores+exp: E[z][q][t] = exp(0.125 * sum_d Q[q,d] K[t,d]); rowsum atomics.
// No smem: fragments loaded directly from gmem (L2-served redundancy).
// Block 128x128, 8 warps (2x4). K-dim = 64 = 4 k16 steps.
// ---------------------------------------------------------------------------
__global__ void __launch_bounds__(256) mma_scores_exp(
    const float* __restrict__ qkv, float* __restrict__ attn)
{
    const int tid = threadIdx.x;
    const int lane = tid & 31, wid = tid >> 5;
    const int warp_m = wid >> 2, warp_n = wid & 3;
    const int z = blockIdx.z, b = z >> 4, h = z & 15;
    const int bm = blockIdx.y * 128, bn = blockIdx.x * 128;
    const float* Qb = qkv + (size_t)b * SEQ * QKVF + h * HD;
    const float* Kb = Qb + EMB;
    float* Cb = attn + (size_t)z * SEQ * SEQ;
    const int r4 = lane >> 2, c4 = lane & 3;

    float acc[4][4][4];
#pragma unroll
    for (int i = 0; i < 4; i++)
#pragma unroll
        for (int j = 0; j < 4; j++)
#pragma unroll
            for (int l = 0; l < 4; l++) acc[i][j][l] = 0.f;

#pragma unroll
    for (int step = 0; step < 4; step++) {
        const int ko = step * 16;
        uint32_t Ah[4][4], Al[4][4];
#pragma unroll
        for (int fm = 0; fm < 4; fm++) {
            const float* p = Qb + (size_t)(bm + warp_m * 64 + fm * 16 + r4) * QKVF + ko + c4 * 2;
            float2 v00 = *(const float2*)p;
            float2 v10 = *(const float2*)(p + 8 * QKVF);
            float2 v01 = *(const float2*)(p + 8);
            float2 v11 = *(const float2*)(p + 8 * QKVF + 8);
            split2(v00.x, v00.y, Ah[fm][0], Al[fm][0]);
            split2(v10.x, v10.y, Ah[fm][1], Al[fm][1]);
            split2(v01.x, v01.y, Ah[fm][2], Al[fm][2]);
            split2(v11.x, v11.y, Ah[fm][3], Al[fm][3]);
        }
#pragma unroll
        for (int fn = 0; fn < 4; fn++) {
            const float* q = Kb + (size_t)(bn + warp_n * 32 + fn * 8 + r4) * QKVF + ko + c4 * 2;
            float2 w0 = *(const float2*)q;
            float2 w1 = *(const float2*)(q + 8);
            uint32_t B0h, B0l, B1h, B1l;
            split2(w0.x, w0.y, B0h, B0l);
            split2(w1.x, w1.y, B1h, B1l);
#pragma unroll
            for (int fm = 0; fm < 4; fm++) {
                mma_bf16(acc[fm][fn], Ah[fm], B0h, B1h);
                mma_bf16(acc[fm][fn], Ah[fm], B0l, B1l);
                mma_bf16(acc[fm][fn], Al[fm], B0h, B1h);
            }
        }
    }

    // epilogue: exp, store E, accumulate row sums
#pragma unroll
    for (int fm = 0; fm < 4; fm++) {
        const int row0 = bm + warp_m * 64 + fm * 16 + r4;
        float rs0 = 0.f, rs1 = 0.f;
#pragma unroll
        for (int fn = 0; fn < 4; fn++) {
            float e0 = __expf(acc[fm][fn][0] * 0.125f);
            float e1 = __expf(acc[fm][fn][1] * 0.125f);
            float e2 = __expf(acc[fm][fn][2] * 0.125f);
            float e3 = __expf(acc[fm][fn][3] * 0.125f);
            rs0 += e0 + e1;
            rs1 += e2 + e3;
            int col = bn + warp_n * 32 + fn * 8 + c4 * 2;
            *(float2*)(Cb + (size_t)row0 * SEQ + col)       = make_float2(e0, e1);
            *(float2*)(Cb + (size_t)(row0 + 8) * SEQ + col) = make_float2(e2, e3);
        }
        rs0 += __shfl_xor_sync(0xffffffffu, rs0, 1);
        rs0 += __shfl_xor_sync(0xffffffffu, rs0, 2);
        rs1 += __shfl_xor_sync(0xffffffffu, rs1, 1);
        rs1 += __shfl_xor_sync(0xffffffffu, rs1, 2);
        if (c4 == 0) {
            atomicAdd(&g_rowsum[(size_t)z * SEQ + row0], rs0);
            atomicAdd(&g_rowsum[(size_t)z * SEQ + row0 + 8], rs1);
        }
    }
}

// ---------------------------------------------------------------------------
// AV + normalize: reads E, computes P = E/rowsum, writes P back to attn,
// O = P @ V. Block 128(M)x64(N), 8 warps (4x2), warp tile 32x32. BK=32.
// A (P) fragments direct from gmem; V staged in smem (transposed, hi/lo).
// ---------------------------------------------------------------------------
__global__ void __launch_bounds__(256) mma_av_norm(
    float* __restrict__ attn, const float* __restrict__ qkv,
    float* __restrict__ out)
{
    __shared__ __align__(16) char sBh[64 * STRB];
    __shared__ __align__(16) char sBl[64 * STRB];

    const int tid = threadIdx.x;
    const int lane = tid & 31, wid = tid >> 5;
    const int warp_m = wid >> 1, warp_n = wid & 1;
    const int z = blockIdx.y, b = z >> 4, h = z & 15;
    const int bm = blockIdx.x * 128;
    float* P = attn + (size_t)z * SEQ * SEQ;
    const float* V = qkv + (size_t)b * SEQ * QKVF + 2 * EMB + h * HD;
    float* O = out + (size_t)b * SEQ * EMB + h * HD;
    const int r4 = lane >> 2, c4 = lane & 3;
    const int vt = tid >> 3, vd = (tid & 7) * 8;

    // reciprocal row sums for this thread's rows
    float inv[2][2];
#pragma unroll
    for (int fm = 0; fm < 2; fm++) {
        int rr = bm + warp_m * 32 + fm * 16 + r4;
        inv[fm][0] = __frcp_rn(g_rowsum[(size_t)z * SEQ + rr]);
        inv[fm][1] = __frcp_rn(g_rowsum[(size_t)z * SEQ + rr + 8]);
    }

    float acc[2][4][4];
#pragma unroll
    for (int i = 0; i < 2; i++)
#pragma unroll
        for (int j = 0; j < 4; j++)
#pragma unroll
            for (int l = 0; l < 4; l++) acc[i][j][l] = 0.f;

    for (int kt = 0; kt < (SEQ >> 5); kt++) {
        // load E fragments, normalize in registers
        float2 f[2][2][4];
#pragma unroll
        for (int fm = 0; fm < 2; fm++) {
#pragma unroll
            for (int s = 0; s < 2; s++) {
                const float* pp = P + (size_t)(bm + warp_m * 32 + fm * 16 + r4) * SEQ
                                    + kt * 32 + s * 16 + c4 * 2;
                f[fm][s][0] = *(const float2*)pp;
                f[fm][s][1] = *(const float2*)(pp + 8 * SEQ);
                f[fm][s][2] = *(const float2*)(pp + 8);
                f[fm][s][3] = *(const float2*)(pp + 8 * SEQ + 8);
                f[fm][s][0].x *= inv[fm][0]; f[fm][s][0].y *= inv[fm][0];
                f[fm][s][1].x *= inv[fm][1]; f[fm][s][1].y *= inv[fm][1];
                f[fm][s][2].x *= inv[fm][0]; f[fm][s][2].y *= inv[fm][0];
                f[fm][s][3].x *= inv[fm][1]; f[fm][s][3].y *= inv[fm][1];
            }
        }
        // V tile registers
        const float* Vp = V + (size_t)(kt * 32 + vt) * QKVF + vd;
        float4 vv0 = *(const float4*)(Vp);
        float4 vv1 = *(const float4*)(Vp + 4);

        __syncthreads();   // prior iteration's smem reads done; all E loads consumed

        // store normalized P (each element exactly once: warp_n==0)
        if (warp_n == 0) {
#pragma unroll
            for (int fm = 0; fm < 2; fm++) {
#pragma unroll
                for (int s = 0; s < 2; s++) {
                    float* pp = P + (size_t)(bm + warp_m * 32 + fm * 16 + r4) * SEQ
                                  + kt * 32 + s * 16 + c4 * 2;
                    *(float2*)pp               = f[fm][s][0];
                    *(float2*)(pp + 8 * SEQ)     = f[fm][s][1];
                    *(float2*)(pp + 8)           = f[fm][s][2];
                    *(float2*)(pp + 8 * SEQ + 8) = f[fm][s][3];
                }
            }
        }

        // stage V transposed hi/lo: sB[d][t]
        {
            float vals[8] = {vv0.x, vv0.y, vv0.z, vv0.w, vv1.x, vv1.y, vv1.z, vv1.w};
#pragma unroll
            for (int j = 0; j < 8; j++) {
                int d = vd + j;
                __nv_bfloat16 bh = __float2bfloat16_rn(vals[j]);
                float rl = vals[j] - __bfloat162float(bh);
                *(__nv_bfloat16*)(sBh + d * STRB + vt * 2) = bh;
                *(__nv_bfloat16*)(sBl + d * STRB + vt * 2) = __float2bfloat16_rn(rl);
            }
        }
        __syncthreads();

        // split P fragments to hi/lo
        uint32_t Ah[2][2][4], Al[2][2][4];
#pragma unroll
        for (int fm = 0; fm < 2; fm++)
#pragma unroll
            for (int s = 0; s < 2; s++)
#pragma unroll
                for (int r = 0; r < 4; r++)
                    split2(f[fm][s][r].x, f[fm][s][r].y, Ah[fm][s][r], Al[fm][s][r]);

#pragma unroll
        for (int s = 0; s < 2; s++) {
            const int kb = s * 32;
#pragma unroll
            for (int fn = 0; fn < 4; fn++) {
                uint32_t bb = (warp_n * 32 + fn * 8 + r4) * STRB + kb + c4 * 4;
                uint32_t Bh0 = *(const uint32_t*)(sBh + bb);
                uint32_t Bh1 = *(const uint32_t*)(sBh + bb + 16);
                uint32_t Bl0 = *(const uint32_t*)(sBl + bb);
                uint32_t Bl1 = *(const uint32_t*)(sBl + bb + 16);
#pragma unroll
                for (int fm = 0; fm < 2; fm++) {
                    mma_bf16(acc[fm][fn], Ah[fm][s], Bh0, Bh1);
                    mma_bf16(acc[fm][fn], Ah[fm][s], Bl0, Bl1);
                    mma_bf16(acc[fm][fn], Al[fm][s], Bh0, Bh1);
                }
            }
        }
    }

    const int cq = c4 * 2;
#pragma unroll
    for (int fm = 0; fm < 2; fm++) {
#pragma unroll
        for (int fn = 0; fn < 4; fn++) {
            int row0 = bm + warp_m * 32 + fm * 16 + r4;
            int col  = warp_n * 32 + fn * 8 + cq;
            *(float2*)(O + (size_t)row0 * EMB + col) =
                make_float2(acc[fm][fn][0], acc[fm][fn][1]);
            *(float2*)(O + (size_t)(row0 + 8) * EMB + col) =
                make_float2(acc[fm][fn][2], acc[fm][fn][3]);
        }
    }
}

// ---------------------------------------------------------------------------
extern "C" void kernel_launch(void* const* d_in, const int* in_sizes, int n_in,
                              void* d_out, int out_size)
{
    const float* x     = (const float*)d_in[0];
    const float* qkv_w = (const float*)d_in[1];
    const float* qkv_b = (const float*)d_in[2];
    const float* out_w = (const float*)d_in[3];
    const float* out_b = (const float*)d_in[4];

    float* out_proj = (float*)d_out;
    float* attn     = (float*)d_out + OUT_ELEMS;

    float* qkv = nullptr;
    float* ao  = nullptr;
    cudaGetSymbolAddress((void**)&qkv, g_qkv);
    cudaGetSymbolAddress((void**)&ao,  g_ao);

    // 1. QKV projection
    mma_gemm_bias<<<dim3(QKVF / 128, TOK / 128), 256>>>(x, qkv_w, qkv_b, qkv, QKVF, EMB);
    // 2. zero rowsums
    zero_rowsum_kernel<<<NROWS / 256, 256>>>();
    // 3. Scores + exp + rowsum
    mma_scores_exp<<<dim3(SEQ / 128, SEQ / 128, BATCH * NH), 256>>>(qkv, attn);
    // 4. AV + normalize (writes P in place, O to scratch)
    mma_av_norm<<<dim3(SEQ / 128, BATCH * NH), 256>>>(attn, qkv, ao);
    // 5. Output projection
    mma_gemm_bias<<<dim3(EMB / 128, TOK / 128), 256>>>(ao, out_w, out_b, out_proj, EMB, EMB);
}